// round 7
// baseline (speedup 1.0000x reference)
#include <cuda_runtime.h>
#include <math.h>

#define Bb      256
#define Nn      8192
#define SD      14
#define ROWS    256
#define THREADS 256
#define CHUNKS  32
#define NTILES  (Bb * CHUNKS)     // 8192
#define GRID    296               // 148 SMs * 2 resident blocks (block 0 = BC/argmin)
#define WORKERS (GRID - 1)        // 295 tile workers

#define TILE_F4      ((ROWS * SD) / 4)   // 896 float4 per stream per tile
#define MAIN_FLOATS  (ROWS * SD)         // 3584
#define HALO_LO_OFF  MAIN_FLOATS         // 3584 (14 floats)
#define HALO_HI_OFF  (MAIN_FLOATS + 14)  // 3598
#define PRED_FLOATS  3616                // padded to 16B multiple
#define TRUE_OFF     PRED_FLOATS
#define STAGE_FLOATS (PRED_FLOATS + MAIN_FLOATS)   // 7200 floats = 28.8KB
#define NSTAGES      3
#define SMEM_BYTES   (NSTAGES * STAGE_FLOATS * 4)  // 86400

// accumulators: 0=weighted data, 1=phys, 2=quat, 3=massflow, 4=bc
__device__ double       g_acc[5];
__device__ unsigned int g_done;

// ---------------------------------------------------------------------------
__device__ __forceinline__ void cp16(void* smem_dst, const void* gsrc) {
    unsigned sa = (unsigned)__cvta_generic_to_shared(smem_dst);
    asm volatile("cp.async.cg.shared.global [%0], [%1], 16;\n" :: "r"(sa), "l"(gsrc));
}
__device__ __forceinline__ void cp4(void* smem_dst, const void* gsrc) {
    unsigned sa = (unsigned)__cvta_generic_to_shared(smem_dst);
    asm volatile("cp.async.ca.shared.global [%0], [%1], 4;\n" :: "r"(sa), "l"(gsrc));
}
#define CP_COMMIT() asm volatile("cp.async.commit_group;\n" ::: "memory")
#define CP_WAIT1()  asm volatile("cp.async.wait_group 1;\n" ::: "memory")

// ---------------------------------------------------------------------------
// issue cp.async loads for one tile (pred main + halos + true main).
// If tile is out of range, commits an empty group (keeps group count uniform).
// ---------------------------------------------------------------------------
__device__ __forceinline__ void issue_tile(int tile, float* stage,
                                           const float* __restrict__ pred,
                                           const float* __restrict__ truev,
                                           int tid)
{
    if (tile < NTILES) {
        const int b = tile >> 5, chunk = tile & (CHUNKS - 1);
        const size_t base = ((size_t)b * Nn + (size_t)chunk * ROWS) * SD;
        const float4* p4 = (const float4*)(pred + base);
        const float4* t4 = (const float4*)(truev + base);
        float4* sp4 = (float4*)stage;
        float4* st4 = (float4*)(stage + TRUE_OFF);

        cp16(sp4 + tid,       p4 + tid);
        cp16(sp4 + tid + 256, p4 + tid + 256);
        cp16(sp4 + tid + 512, p4 + tid + 512);
        cp16(st4 + tid,       t4 + tid);
        cp16(st4 + tid + 256, t4 + tid + 256);
        cp16(st4 + tid + 512, t4 + tid + 512);
        if (tid < TILE_F4 - 768) {
            cp16(sp4 + tid + 768, p4 + tid + 768);
            cp16(st4 + tid + 768, t4 + tid + 768);
        }
        if (chunk > 0 && tid >= 128 && tid < 128 + SD)
            cp4(stage + HALO_LO_OFF + (tid - 128), pred + base - SD + (tid - 128));
        if (chunk < CHUNKS - 1 && tid >= 160 && tid < 160 + SD)
            cp4(stage + HALO_HI_OFF + (tid - 160), pred + base + MAIN_FLOATS + (tid - 160));
    }
    CP_COMMIT();
}

// ---------------------------------------------------------------------------
// Single persistent kernel.
//   block 0        : argmin|t| + boundary-condition loss (g_acc[4])
//   blocks 1..295  : tile streaming for data/phys/quat/massflow losses
//   last ticket    : finalize -> out[6], reset accumulators for next replay
// ---------------------------------------------------------------------------
__global__ __launch_bounds__(THREADS, 2)
void k_main(const float* __restrict__ pred,
            const float* __restrict__ truev,
            const float* __restrict__ t,
            const float* __restrict__ ctrl,
            float* __restrict__ out)
{
    extern __shared__ __align__(16) float sm[];
    __shared__ double red[THREADS / 32][5];
    __shared__ float  svals[THREADS];
    __shared__ int    sidx[THREADS];

    const int tid = threadIdx.x;
    float wD = 0.f, sP = 0.f, sQ = 0.f, sMF = 0.f, sBC = 0.f;

    if (blockIdx.x == 0) {
        // ---- argmin |t[0,:,0]| ----
        const float4* t4 = (const float4*)t;
        float best = 3.402823466e+38f;
        int   bi   = 0;
        #pragma unroll
        for (int j = 0; j < 8; j++) {
            float4 v = t4[tid * 8 + j];
            float a[4] = { fabsf(v.x), fabsf(v.y), fabsf(v.z), fabsf(v.w) };
            #pragma unroll
            for (int k = 0; k < 4; k++) {
                int idx = tid * 32 + j * 4 + k;
                if (a[k] < best) { best = a[k]; bi = idx; }
            }
        }
        svals[tid] = best;  sidx[tid] = bi;
        __syncthreads();
        for (int s = THREADS / 2; s > 0; s >>= 1) {
            if (tid < s) {
                float v2 = svals[tid + s];
                int   i2 = sidx[tid + s];
                if (v2 < svals[tid] || (v2 == svals[tid] && i2 < sidx[tid])) {
                    svals[tid] = v2;  sidx[tid] = i2;
                }
            }
            __syncthreads();
        }
        const int tidx = sidx[0];

        // ---- boundary-condition loss: thread b handles batch b ----
        const float* pr = pred  + ((size_t)tid * Nn + tidx) * SD;
        const float* tr = truev + ((size_t)tid * Nn + tidx) * SD;
        #pragma unroll
        for (int i = 0; i < SD; i++) {
            float d = pr[i] - tr[i];
            sBC = fmaf(d, d, sBC);
        }
    } else {
        // ---- tile workers ----
        const int wid = blockIdx.x - 1;

        issue_tile(wid,               sm,                    pred, truev, tid);
        issue_tile(wid + WORKERS,     sm + STAGE_FLOATS,     pred, truev, tid);

        int stage = 0;
        for (int tile = wid; tile < NTILES; tile += WORKERS) {
            CP_WAIT1();                 // oldest of the <=2 pending groups done
            __syncthreads();

            float* buf = sm + stage * STAGE_FLOATS;
            issue_tile(tile + 2 * WORKERS,
                       sm + ((stage + 2) % NSTAGES) * STAGE_FLOATS,
                       pred, truev, tid);

            const int chunk = tile & (CHUNKS - 1);
            const int n0    = chunk * ROWS;
            const size_t rowoff = ((size_t)(tile >> 5) * Nn + n0);

            // control row: per-thread float4 (latency hidden by data-loss math)
            const float4 u4 = ((const float4*)(ctrl + rowoff * 4))[tid];

            // ---- weighted data loss (pred/true both in smem) ----
            {
                const float4* bp4 = (const float4*)buf;
                const float4* bt4 = (const float4*)(buf + TRUE_OFF);
                #pragma unroll
                for (int j = 0; j < 4; j++) {
                    const int i = tid + j * 256;
                    if (j == 3 && i >= TILE_F4) break;
                    float4 pv = bp4[i];
                    float4 tv = bt4[i];
                    unsigned e = 4u * (unsigned)i;
                    unsigned r = e / 14u;
                    unsigned c = e - r * 14u;
                    const float pe[4] = { pv.x, pv.y, pv.z, pv.w };
                    const float te[4] = { tv.x, tv.y, tv.z, tv.w };
                    #pragma unroll
                    for (int k = 0; k < 4; k++) {
                        float d  = pe[k] - te[k];
                        float w  = (c < 6u) ? (1.0f / 6.0f)
                                 : ((c == 13u) ? 1.0f : (1.0f / 7.0f));
                        wD = fmaf(d * d, w, wD);
                        if (++c == 14u) { c = 0u; ++r; }
                    }
                }
            }

            // ---- per-row physics ----
            const int n = n0 + tid;
            const float* s = buf + tid * SD;

            float sr[SD];
            {
                const float2* s2 = (const float2*)s;
                #pragma unroll
                for (int k = 0; k < 7; k++) {
                    float2 v = s2[k];
                    sr[2 * k] = v.x;  sr[2 * k + 1] = v.y;
                }
            }

            const bool fwd = (n == 0), bwd = (n == Nn - 1);
            const float* hip = (tid < ROWS - 1) ? (buf + (tid + 1) * SD)
                                                : (buf + HALO_HI_OFF);
            const float* lop = (tid > 0)        ? (buf + (tid - 1) * SD)
                                                : (buf + HALO_LO_OFF);
            if (fwd) lop = s;
            if (bwd) hip = s;

            float ta, tb2;
            if (fwd)      { ta = t[0];      tb2 = t[1];      }
            else if (bwd) { ta = t[Nn - 2]; tb2 = t[Nn - 1]; }
            else          { ta = t[n - 1];  tb2 = t[n + 1];  }
            const float inv_dt = 1.0f / (tb2 - ta + 1e-12f);

            const float q0 = sr[6], q1 = sr[7], q2 = sr[8], q3 = sr[9];
            const float qn  = sqrtf(q0 * q0 + q1 * q1 + q2 * q2 + q3 * q3);
            const float dqn = qn - 1.0f;
            sQ += dqn * dqn;

            if (n < Nn - 1) {
                float dmf = hip[13] - sr[13];
                if (dmf > 0.f) sMF += dmf;
            }

            const float vx = sr[3],  vy = sr[4],  vz = sr[5];
            const float wx = sr[10], wy = sr[11], wz = sr[12];
            const float thrust = u4.x * 1000000.0f;
            const float bzx = 2.0f * (q1 * q3 + q0 * q2);
            const float bzy = 2.0f * (q2 * q3 - q0 * q1);
            const float bzz = 1.0f - 2.0f * (q1 * q1 + q2 * q2);
            const float speed = sqrtf(vx * vx + vy * vy + vz * vz + 1e-12f);
            const float dragc = -0.30625f * speed;
            const float invm  = 1.0f / sr[13];

            float dyn[SD];
            dyn[0]  = vx; dyn[1] = vy; dyn[2] = vz;
            dyn[3]  = (thrust * bzx + dragc * vx) * invm;
            dyn[4]  = (thrust * bzy + dragc * vy) * invm;
            dyn[5]  = (thrust * bzz + dragc * vz) * invm - 9.80665f;
            dyn[6]  = 0.5f * (-q1 * wx - q2 * wy - q3 * wz);
            dyn[7]  = 0.5f * ( q0 * wx + q2 * wz - q3 * wy);
            dyn[8]  = 0.5f * ( q0 * wy - q1 * wz + q3 * wx);
            dyn[9]  = 0.5f * ( q0 * wz + q1 * wy - q2 * wx);
            dyn[10] = (u4.y * 10000.0f + 4000.0f * wy * wz) * (1.0f / 5000.0f);
            dyn[11] = (u4.z * 10000.0f - 4000.0f * wz * wx) * (1.0f / 5000.0f);
            dyn[12] = (u4.w * 10000.0f) * (1.0f / 1000.0f);
            dyn[13] = -thrust * (1.0f / (300.0f * 9.80665f));

            float sPl = 0.f;
            #pragma unroll
            for (int i = 0; i < SD; i++) {
                float rr = (hip[i] - lop[i]) * inv_dt - dyn[i];
                sPl = fmaf(rr, rr, sPl);
            }
            sP += sPl;

            stage = (stage + 1) % NSTAGES;
            __syncthreads();           // stage reuse guard before next wait/issue
        }
    }

    // ---- reduction: fp32 intra-warp, fp64 cross-warp + global atomics ----
    float vf[5] = { wD, sP, sQ, sMF, sBC };
    const int lane = tid & 31, warp = tid >> 5;
    #pragma unroll
    for (int off = 16; off > 0; off >>= 1)
        #pragma unroll
        for (int j = 0; j < 5; j++)
            vf[j] += __shfl_down_sync(0xffffffffu, vf[j], off);
    if (lane == 0)
        #pragma unroll
        for (int j = 0; j < 5; j++) red[warp][j] = (double)vf[j];
    __syncthreads();

    if (warp == 0) {
        double vd[5];
        #pragma unroll
        for (int j = 0; j < 5; j++)
            vd[j] = (lane < THREADS / 32) ? red[lane][j] : 0.0;
        #pragma unroll
        for (int off = 4; off > 0; off >>= 1)
            #pragma unroll
            for (int j = 0; j < 5; j++)
                vd[j] += __shfl_down_sync(0xffffffffu, vd[j], off);
        if (lane == 0) {
            #pragma unroll
            for (int j = 0; j < 5; j++)
                if (vd[j] != 0.0) atomicAdd(&g_acc[j], vd[j]);

            __threadfence();
            unsigned int ticket = atomicAdd(&g_done, 1u);
            if (ticket == GRID - 1) {
                const double BN = (double)Bb * (double)Nn;
                double L_data = g_acc[0] / BN;
                double L_phys = g_acc[1] / (BN * 14.0);
                double L_quat = g_acc[2] / BN;
                double L_mf   = g_acc[3] / ((double)Bb * (double)(Nn - 1));
                double L_bc   = g_acc[4] / ((double)Bb * 14.0);
                double total  = L_data + 0.1 * L_phys + L_bc
                              + 0.01 * L_quat + 0.01 * L_mf;
                out[0] = (float)total;
                out[1] = (float)L_data;
                out[2] = (float)L_phys;
                out[3] = (float)L_bc;
                out[4] = (float)L_quat;
                out[5] = (float)L_mf;
                // reset for next graph replay
                #pragma unroll
                for (int j = 0; j < 5; j++) g_acc[j] = 0.0;
                g_done = 0u;
            }
        }
    }
}

// ---------------------------------------------------------------------------
extern "C" void kernel_launch(void* const* d_in, const int* in_sizes, int n_in,
                              void* d_out, int out_size)
{
    const float* pred = (const float*)d_in[0];
    const float* tru  = (const float*)d_in[1];
    const float* t    = (const float*)d_in[2];
    const float* ctrl = (const float*)d_in[3];
    float* out = (float*)d_out;

    static bool attr_set = false;
    if (!attr_set) {
        cudaFuncSetAttribute(k_main,
                             cudaFuncAttributeMaxDynamicSharedMemorySize,
                             SMEM_BYTES);
        attr_set = true;
    }
    k_main<<<GRID, THREADS, SMEM_BYTES>>>(pred, tru, t, ctrl, out);
}

// round 9
// speedup vs baseline: 1.0810x; 1.0810x over previous
#include <cuda_runtime.h>
#include <math.h>

#define Bb      256
#define Nn      8192
#define SD      14
#define ROWS    256
#define THREADS 256
#define CHUNKS  32
#define NTILES  (Bb * CHUNKS)     // 8192
#define GRID    444               // block 0 = argmin+BC, 1..443 = tile workers
#define WORKERS (GRID - 1)

#define TILE_F4      ((ROWS * SD) / 4)   // 896
#define MAIN_FLOATS  (ROWS * SD)         // 3584
#define HALO_LO_OFF  MAIN_FLOATS         // 3584 (14 floats)
#define HALO_HI_OFF  (MAIN_FLOATS + 14)  // 3598
#define BUF_FLOATS   3616

// accumulators: 0=weighted data, 1=phys, 2=quat, 3=massflow, 4=bc
__device__ double       g_acc[5];
__device__ unsigned int g_done;

// ---------------------------------------------------------------------------
// load one tile's pred data into registers (coalesced LDG.128 + halo LDG.32)
// ---------------------------------------------------------------------------
__device__ __forceinline__ void load_pred(int tile, const float* __restrict__ pred,
                                          int tid, float4 p[4],
                                          float& hlo, float& hhi)
{
    const int b = tile >> 5, chunk = tile & (CHUNKS - 1);
    const size_t base = ((size_t)b * Nn + (size_t)chunk * ROWS) * SD;
    const float4* p4 = (const float4*)(pred + base);
    p[0] = p4[tid];
    p[1] = p4[tid + 256];
    p[2] = p4[tid + 512];
    if (tid < TILE_F4 - 768) p[3] = p4[tid + 768];
    if (chunk > 0 && tid >= 128 && tid < 128 + SD)
        hlo = pred[base - SD + (tid - 128)];
    if (chunk < CHUNKS - 1 && tid >= 160 && tid < 160 + SD)
        hhi = pred[base + MAIN_FLOATS + (tid - 160)];
}

__device__ __forceinline__ void store_pred(float* buf, int tid, const float4 p[4],
                                           float hlo, float hhi)
{
    float4* b4 = (float4*)buf;
    b4[tid]       = p[0];
    b4[tid + 256] = p[1];
    b4[tid + 512] = p[2];
    if (tid < TILE_F4 - 768) b4[tid + 768] = p[3];
    if (tid >= 128 && tid < 128 + SD) buf[HALO_LO_OFF + (tid - 128)] = hlo;
    if (tid >= 160 && tid < 160 + SD) buf[HALO_HI_OFF + (tid - 160)] = hhi;
}

// ---------------------------------------------------------------------------
// Single persistent kernel.
//   block 0       : argmin|t| + boundary-condition loss
//   blocks 1..443 : tile streaming (data/phys/quat/massflow)
//   last ticket   : finalize -> out[6], reset accumulators for next replay
// ---------------------------------------------------------------------------
__global__ __launch_bounds__(THREADS, 3)
void k_main(const float* __restrict__ pred,
            const float* __restrict__ truev,
            const float* __restrict__ t,
            const float* __restrict__ ctrl,
            float* __restrict__ out)
{
    __shared__ __align__(16) float buf[BUF_FLOATS];
    __shared__ double red[THREADS / 32][5];

    const int tid = threadIdx.x;
    float wD = 0.f, sP = 0.f, sQ = 0.f, sMF = 0.f, sBC = 0.f;

    if (blockIdx.x == 0) {
        // ---- argmin |t[0,:,0]| ----
        __shared__ float svals[THREADS];
        __shared__ int   sidx[THREADS];
        const float4* t4 = (const float4*)t;
        float best = 3.402823466e+38f;
        int   bi   = 0;
        #pragma unroll
        for (int j = 0; j < 8; j++) {
            float4 v = t4[tid * 8 + j];
            float a[4] = { fabsf(v.x), fabsf(v.y), fabsf(v.z), fabsf(v.w) };
            #pragma unroll
            for (int k = 0; k < 4; k++) {
                int idx = tid * 32 + j * 4 + k;
                if (a[k] < best) { best = a[k]; bi = idx; }
            }
        }
        svals[tid] = best;  sidx[tid] = bi;
        __syncthreads();
        for (int s = THREADS / 2; s > 0; s >>= 1) {
            if (tid < s) {
                float v2 = svals[tid + s];
                int   i2 = sidx[tid + s];
                if (v2 < svals[tid] || (v2 == svals[tid] && i2 < sidx[tid])) {
                    svals[tid] = v2;  sidx[tid] = i2;
                }
            }
            __syncthreads();
        }
        const int tidx = sidx[0];

        // ---- boundary-condition loss: thread b handles batch b ----
        const float* pr = pred  + ((size_t)tid * Nn + tidx) * SD;
        const float* tr = truev + ((size_t)tid * Nn + tidx) * SD;
        #pragma unroll
        for (int i = 0; i < SD; i++) {
            float d = pr[i] - tr[i];
            sBC = fmaf(d, d, sBC);
        }
    } else {
        // ---- tile workers: register-pipelined demand-LDG streaming ----
        const int wid = blockIdx.x - 1;

        float4 p[4];
        float  hlo = 0.f, hhi = 0.f;
        load_pred(wid, pred, tid, p, hlo, hhi);

        for (int tile = wid; tile < NTILES; tile += WORKERS) {
            __syncthreads();                    // buf free (prev FD done)
            store_pred(buf, tid, p, hlo, hhi);

            const int chunk = tile & (CHUNKS - 1);
            const int n0    = chunk * ROWS;
            const size_t rowoff = ((size_t)(tile >> 5) * Nn + n0);

            // true + control for THIS tile (demand, high MLP)
            const float4* t4g = (const float4*)(truev + rowoff * SD);
            float4 tt[4];
            tt[0] = t4g[tid];
            tt[1] = t4g[tid + 256];
            tt[2] = t4g[tid + 512];
            if (tid < TILE_F4 - 768) tt[3] = t4g[tid + 768];
            const float4 u4 = ((const float4*)(ctrl + rowoff * 4))[tid];

            // ---- weighted data loss from registers ----
            #pragma unroll
            for (int j = 0; j < 4; j++) {
                const int i = tid + j * 256;
                if (j == 3 && i >= TILE_F4) break;
                unsigned e = 4u * (unsigned)i;
                unsigned r = e / 14u;
                unsigned c = e - r * 14u;
                const float pe[4] = { p[j].x, p[j].y, p[j].z, p[j].w };
                const float te[4] = { tt[j].x, tt[j].y, tt[j].z, tt[j].w };
                #pragma unroll
                for (int k = 0; k < 4; k++) {
                    float d = pe[k] - te[k];
                    float w = (c < 6u) ? (1.0f / 6.0f)
                            : ((c == 13u) ? 1.0f : (1.0f / 7.0f));
                    wD = fmaf(d * d, w, wD);
                    if (++c == 14u) { c = 0u; ++r; }
                }
            }

            // prefetch next tile's pred (in flight across FD phase)
            if (tile + WORKERS < NTILES) {
                hlo = hhi = 0.f;
                load_pred(tile + WORKERS, pred, tid, p, hlo, hhi);
            }

            __syncthreads();                    // buf filled

            // ---- per-row physics from smem ----
            const int n = n0 + tid;
            const float* s = buf + tid * SD;

            float sr[SD];
            {
                const float2* s2 = (const float2*)s;
                #pragma unroll
                for (int k = 0; k < 7; k++) {
                    float2 v = s2[k];
                    sr[2 * k] = v.x;  sr[2 * k + 1] = v.y;
                }
            }

            const bool fwd = (n == 0), bwd = (n == Nn - 1);
            const float* hip = (tid < ROWS - 1) ? (buf + (tid + 1) * SD)
                                                : (buf + HALO_HI_OFF);
            const float* lop = (tid > 0)        ? (buf + (tid - 1) * SD)
                                                : (buf + HALO_LO_OFF);
            if (fwd) lop = s;
            if (bwd) hip = s;

            float ta, tb2;
            if (fwd)      { ta = t[0];      tb2 = t[1];      }
            else if (bwd) { ta = t[Nn - 2]; tb2 = t[Nn - 1]; }
            else          { ta = t[n - 1];  tb2 = t[n + 1];  }
            const float inv_dt = 1.0f / (tb2 - ta + 1e-12f);

            const float q0 = sr[6], q1 = sr[7], q2 = sr[8], q3 = sr[9];
            const float qn  = sqrtf(q0 * q0 + q1 * q1 + q2 * q2 + q3 * q3);
            const float dqn = qn - 1.0f;
            sQ += dqn * dqn;

            if (n < Nn - 1) {
                float dmf = hip[13] - sr[13];
                if (dmf > 0.f) sMF += dmf;
            }

            const float vx = sr[3],  vy = sr[4],  vz = sr[5];
            const float wx = sr[10], wy = sr[11], wz = sr[12];
            const float thrust = u4.x * 1000000.0f;
            const float bzx = 2.0f * (q1 * q3 + q0 * q2);
            const float bzy = 2.0f * (q2 * q3 - q0 * q1);
            const float bzz = 1.0f - 2.0f * (q1 * q1 + q2 * q2);
            const float speed = sqrtf(vx * vx + vy * vy + vz * vz + 1e-12f);
            const float dragc = -0.30625f * speed;
            const float invm  = 1.0f / sr[13];

            float dyn[SD];
            dyn[0]  = vx; dyn[1] = vy; dyn[2] = vz;
            dyn[3]  = (thrust * bzx + dragc * vx) * invm;
            dyn[4]  = (thrust * bzy + dragc * vy) * invm;
            dyn[5]  = (thrust * bzz + dragc * vz) * invm - 9.80665f;
            dyn[6]  = 0.5f * (-q1 * wx - q2 * wy - q3 * wz);
            dyn[7]  = 0.5f * ( q0 * wx + q2 * wz - q3 * wy);
            dyn[8]  = 0.5f * ( q0 * wy - q1 * wz + q3 * wx);
            dyn[9]  = 0.5f * ( q0 * wz + q1 * wy - q2 * wx);
            dyn[10] = (u4.y * 10000.0f + 4000.0f * wy * wz) * (1.0f / 5000.0f);
            dyn[11] = (u4.z * 10000.0f - 4000.0f * wz * wx) * (1.0f / 5000.0f);
            dyn[12] = (u4.w * 10000.0f) * (1.0f / 1000.0f);
            dyn[13] = -thrust * (1.0f / (300.0f * 9.80665f));

            float sPl = 0.f;
            #pragma unroll
            for (int i = 0; i < SD; i++) {
                float rr = (hip[i] - lop[i]) * inv_dt - dyn[i];
                sPl = fmaf(rr, rr, sPl);
            }
            sP += sPl;
        }
    }

    // ---- reduction: fp32 intra-warp, fp64 cross-warp + global atomics ----
    float vf[5] = { wD, sP, sQ, sMF, sBC };
    const int lane = tid & 31, warp = tid >> 5;
    #pragma unroll
    for (int off = 16; off > 0; off >>= 1)
        #pragma unroll
        for (int j = 0; j < 5; j++)
            vf[j] += __shfl_down_sync(0xffffffffu, vf[j], off);
    if (lane == 0)
        #pragma unroll
        for (int j = 0; j < 5; j++) red[warp][j] = (double)vf[j];
    __syncthreads();

    if (warp == 0) {
        double vd[5];
        #pragma unroll
        for (int j = 0; j < 5; j++)
            vd[j] = (lane < THREADS / 32) ? red[lane][j] : 0.0;
        #pragma unroll
        for (int off = 4; off > 0; off >>= 1)
            #pragma unroll
            for (int j = 0; j < 5; j++)
                vd[j] += __shfl_down_sync(0xffffffffu, vd[j], off);
        if (lane == 0) {
            #pragma unroll
            for (int j = 0; j < 5; j++)
                atomicAdd(&g_acc[j], vd[j]);

            __threadfence();
            unsigned int ticket = atomicAdd(&g_done, 1u);
            if (ticket == GRID - 1) {
                const double BN = (double)Bb * (double)Nn;
                double L_data = g_acc[0] / BN;
                double L_phys = g_acc[1] / (BN * 14.0);
                double L_quat = g_acc[2] / BN;
                double L_mf   = g_acc[3] / ((double)Bb * (double)(Nn - 1));
                double L_bc   = g_acc[4] / ((double)Bb * 14.0);
                double total  = L_data + 0.1 * L_phys + L_bc
                              + 0.01 * L_quat + 0.01 * L_mf;
                out[0] = (float)total;
                out[1] = (float)L_data;
                out[2] = (float)L_phys;
                out[3] = (float)L_bc;
                out[4] = (float)L_quat;
                out[5] = (float)L_mf;
                // reset for next graph replay
                #pragma unroll
                for (int j = 0; j < 5; j++) g_acc[j] = 0.0;
                g_done = 0u;
            }
        }
    }
}

// ---------------------------------------------------------------------------
extern "C" void kernel_launch(void* const* d_in, const int* in_sizes, int n_in,
                              void* d_out, int out_size)
{
    const float* pred = (const float*)d_in[0];
    const float* tru  = (const float*)d_in[1];
    const float* t    = (const float*)d_in[2];
    const float* ctrl = (const float*)d_in[3];
    float* out = (float*)d_out;

    k_main<<<GRID, THREADS>>>(pred, tru, t, ctrl, out);
}